// round 1
// baseline (speedup 1.0000x reference)
#include <cuda_runtime.h>
#include <cuda_bf16.h>
#include <math.h>

// Problem constants
constexpr int BATCH = 4;
constexpr int CIN   = 128;
constexpr int COUT  = 64;
constexpr int HH    = 128;
constexpr int WW    = 128;
constexpr int HWSZ  = HH * WW;
constexpr int DG    = 16;
constexpr int KK    = 9;

// Scratch (static device buffers; allocation APIs are forbidden)
__device__ float g_t1[(size_t)BATCH * COUT * HWSZ];
__device__ float g_t2[(size_t)BATCH * COUT * HWSZ];
__device__ float g_o4[(size_t)BATCH * (27 * DG) * HWSZ];   // 432 channels
__device__ float g_wt[(size_t)CIN * KK * COUT];            // transposed deform weight [cin][k][o]

// ---------------------------------------------------------------------------
// Transpose deform weight (COUT, CIN, 3, 3) -> [cin][k][o] for coalesced smem loads
// ---------------------------------------------------------------------------
__global__ void transpose_weight_k(const float* __restrict__ w, float* __restrict__ wt) {
    int idx = blockIdx.x * blockDim.x + threadIdx.x;
    int n = CIN * KK * COUT;
    if (idx >= n) return;
    int o   = idx % COUT;
    int k   = (idx / COUT) % KK;
    int cin = idx / (COUT * KK);
    wt[idx] = w[((size_t)o * CIN + cin) * KK + k];
}

// ---------------------------------------------------------------------------
// Direct 3x3 conv, pad=1, stride=1, optional leaky-relu(0.1).
// Tile: full row width (128) x 4 rows. blockDim = (32,4) = 128 threads.
// Each thread: 4 horizontally consecutive pixels x 8 output channels.
// grid = (H/4, Cout/8, B)
// ---------------------------------------------------------------------------
__global__ void conv3x3_k(const float* __restrict__ in, const float* __restrict__ wgt,
                          const float* __restrict__ bias, float* __restrict__ out,
                          int Cin, int lrelu) {
    const int ytile = blockIdx.x;       // 0..31
    const int ocg   = blockIdx.y;       // Cout/8 groups
    const int b     = blockIdx.z;
    const int tx    = threadIdx.x;      // 0..31
    const int ty    = threadIdx.y;      // 0..3
    const int tid   = ty * 32 + tx;
    const int y0    = ytile * 4;
    const int oc0   = ocg * 8;
    const int Cout_ = gridDim.y * 8;

    __shared__ __align__(16) float s_in[6 * 132];
    __shared__ float s_w[72];

    float acc[8][4];
#pragma unroll
    for (int o = 0; o < 8; o++)
#pragma unroll
        for (int j = 0; j < 4; j++) acc[o][j] = 0.f;

    const float* inb = in + (size_t)b * Cin * HWSZ;

    for (int ci = 0; ci < Cin; ci++) {
        __syncthreads();
        // Load 6x130 input tile (rows y0-1 .. y0+4, cols -1 .. 128) with zero padding.
        const float* inc = inb + (size_t)ci * HWSZ;
        for (int idx = tid; idx < 6 * 130; idx += 128) {
            int r  = idx / 130;
            int c  = idx % 130;
            int gy = y0 - 1 + r;
            int gx = c - 1;
            float v = 0.f;
            if (gy >= 0 && gy < HH && gx >= 0 && gx < WW) v = inc[gy * WW + gx];
            s_in[r * 132 + c] = v;
        }
        if (tid < 72) {
            int o = tid / 9, k = tid % 9;
            s_w[tid] = wgt[((size_t)(oc0 + o) * Cin + ci) * 9 + k];
        }
        __syncthreads();

        // Register-load the 3x6 input window for this thread's 4 pixels.
        float a[3][6];
#pragma unroll
        for (int r = 0; r < 3; r++) {
            const float* row = &s_in[(ty + r) * 132 + tx * 4];
#pragma unroll
            for (int c = 0; c < 6; c++) a[r][c] = row[c];
        }
#pragma unroll
        for (int o = 0; o < 8; o++) {
#pragma unroll
            for (int r = 0; r < 3; r++) {
#pragma unroll
                for (int s = 0; s < 3; s++) {
                    float wv = s_w[o * 9 + r * 3 + s];
#pragma unroll
                    for (int j = 0; j < 4; j++)
                        acc[o][j] = fmaf(a[r][j + s], wv, acc[o][j]);
                }
            }
        }
    }

    // Store (with bias, optional leaky relu).
    const int px0 = tx * 4;
    const int yy  = y0 + ty;
#pragma unroll
    for (int o = 0; o < 8; o++) {
        float bv = bias[oc0 + o];
        float* op = out + ((size_t)b * Cout_ + oc0 + o) * HWSZ + yy * WW + px0;
#pragma unroll
        for (int j = 0; j < 4; j++) {
            float v = acc[o][j] + bv;
            if (lrelu) v = (v >= 0.f) ? v : 0.1f * v;
            op[j] = v;
        }
    }
}

// ---------------------------------------------------------------------------
// Deformable conv (fused tanh/sigmoid on raw conv4 output).
// Thread = one pixel, 64 output-channel accumulators in registers.
// Weights for one deform group (8 cin x 9 k x 64 oc) staged in smem.
// blockDim = (32,4); grid = (W/32, H/4, B)
// ---------------------------------------------------------------------------
__global__ void deform_k(const float* __restrict__ x, const float* __restrict__ o4,
                         const float* __restrict__ wt, const float* __restrict__ bias,
                         float* __restrict__ out) {
    const int tx = threadIdx.x, ty = threadIdx.y;
    const int tid = ty * 32 + tx;
    const int b   = blockIdx.z;
    const int px  = blockIdx.x * 32 + tx;
    const int py  = blockIdx.y * 4 + ty;
    const int p   = py * WW + px;

    __shared__ __align__(16) float s_w[8 * 9 * 64];  // [c][k][o]

    float acc[64];
#pragma unroll
    for (int o = 0; o < 64; o++) acc[o] = 0.f;

    const float* xb = x + (size_t)b * CIN * HWSZ;
    const float* ob = o4 + (size_t)b * (27 * DG) * HWSZ;

    for (int g = 0; g < DG; g++) {
        __syncthreads();
        const float* wg = wt + (size_t)g * 8 * 9 * 64;
        for (int i = tid; i < 8 * 9 * 64; i += 128) s_w[i] = wg[i];
        __syncthreads();

        const float* xg = xb + (size_t)g * 8 * HWSZ;

        for (int k = 0; k < KK; k++) {
            float dy = 10.f * tanhf(ob[(size_t)(g * 18 + 2 * k) * HWSZ + p]);
            float dx = 10.f * tanhf(ob[(size_t)(g * 18 + 2 * k + 1) * HWSZ + p]);
            float mv = ob[(size_t)(288 + g * 9 + k) * HWSZ + p];
            float m  = 1.f / (1.f + __expf(-mv));

            float fy = (float)py - 1.f + (float)(k / 3) + dy;
            float fx = (float)px - 1.f + (float)(k % 3) + dx;
            float y0f = floorf(fy), x0f = floorf(fx);
            float ly = fy - y0f, lx = fx - x0f;
            int y0 = (int)y0f, x0 = (int)x0f;
            int y1 = y0 + 1, x1 = x0 + 1;

            bool vy0 = (y0 >= 0) && (y0 < HH);
            bool vy1 = (y1 >= 0) && (y1 < HH);
            bool vx0 = (x0 >= 0) && (x0 < WW);
            bool vx1 = (x1 >= 0) && (x1 < WW);

            float w00 = (1.f - ly) * (1.f - lx) * ((vy0 && vx0) ? m : 0.f);
            float w01 = (1.f - ly) * lx         * ((vy0 && vx1) ? m : 0.f);
            float w10 = ly * (1.f - lx)         * ((vy1 && vx0) ? m : 0.f);
            float w11 = ly * lx                 * ((vy1 && vx1) ? m : 0.f);

            int yc0 = min(max(y0, 0), HH - 1);
            int yc1 = min(max(y1, 0), HH - 1);
            int xc0 = min(max(x0, 0), WW - 1);
            int xc1 = min(max(x1, 0), WW - 1);
            int i00 = yc0 * WW + xc0, i01 = yc0 * WW + xc1;
            int i10 = yc1 * WW + xc0, i11 = yc1 * WW + xc1;

            for (int c = 0; c < 8; c++) {
                const float* xc = xg + (size_t)c * HWSZ;
                float v = w00 * xc[i00] + w01 * xc[i01] + w10 * xc[i10] + w11 * xc[i11];
                const float4* wp = (const float4*)&s_w[(c * 9 + k) * 64];
#pragma unroll
                for (int q = 0; q < 16; q++) {
                    float4 wq = wp[q];
                    acc[q * 4 + 0] = fmaf(v, wq.x, acc[q * 4 + 0]);
                    acc[q * 4 + 1] = fmaf(v, wq.y, acc[q * 4 + 1]);
                    acc[q * 4 + 2] = fmaf(v, wq.z, acc[q * 4 + 2]);
                    acc[q * 4 + 3] = fmaf(v, wq.w, acc[q * 4 + 3]);
                }
            }
        }
    }

    float* outb = out + (size_t)b * COUT * HWSZ + p;
#pragma unroll
    for (int o = 0; o < 64; o++) outb[(size_t)o * HWSZ] = acc[o] + bias[o];
}

// ---------------------------------------------------------------------------
// Launcher
// ---------------------------------------------------------------------------
extern "C" void kernel_launch(void* const* d_in, const int* in_sizes, int n_in,
                              void* d_out, int out_size) {
    const float* x          = (const float*)d_in[0];
    const float* extra_feat = (const float*)d_in[1];
    const float* w1 = (const float*)d_in[2];
    const float* b1 = (const float*)d_in[3];
    const float* w2 = (const float*)d_in[4];
    const float* b2 = (const float*)d_in[5];
    const float* w3 = (const float*)d_in[6];
    const float* b3 = (const float*)d_in[7];
    const float* w4 = (const float*)d_in[8];
    const float* b4 = (const float*)d_in[9];
    const float* weight = (const float*)d_in[10];
    const float* bias   = (const float*)d_in[11];
    float* out = (float*)d_out;

    float *t1, *t2, *o4, *wt;
    cudaGetSymbolAddress((void**)&t1, g_t1);
    cudaGetSymbolAddress((void**)&t2, g_t2);
    cudaGetSymbolAddress((void**)&o4, g_o4);
    cudaGetSymbolAddress((void**)&wt, g_wt);

    dim3 blk(32, 4);

    // Transpose deform weight for the final stage (runs concurrently-safe: only writes g_wt)
    {
        int n = CIN * KK * COUT;
        transpose_weight_k<<<(n + 255) / 256, 256>>>(weight, wt);
    }

    // conv1: extra_feat (192ch) -> t1 (64ch), lrelu
    conv3x3_k<<<dim3(HH / 4, COUT / 8, BATCH), blk>>>(extra_feat, w1, b1, t1, 3 * COUT, 1);
    // conv2: t1 -> t2, lrelu
    conv3x3_k<<<dim3(HH / 4, COUT / 8, BATCH), blk>>>(t1, w2, b2, t2, COUT, 1);
    // conv3: t2 -> t1, lrelu
    conv3x3_k<<<dim3(HH / 4, COUT / 8, BATCH), blk>>>(t2, w3, b3, t1, COUT, 1);
    // conv4: t1 -> o4 (432ch), no activation (fused into deform)
    conv3x3_k<<<dim3(HH / 4, (27 * DG) / 8, BATCH), blk>>>(t1, w4, b4, o4, COUT, 0);
    // deformable conv: x + o4 -> out
    deform_k<<<dim3(WW / 32, HH / 4, BATCH), blk>>>(x, o4, wt, bias, out);
}

// round 3
// speedup vs baseline: 1.4907x; 1.4907x over previous
#include <cuda_runtime.h>
#include <cuda_bf16.h>
#include <math.h>

// Problem constants
constexpr int BATCH = 4;
constexpr int CIN   = 128;
constexpr int COUT  = 64;
constexpr int HH    = 128;
constexpr int WW    = 128;
constexpr int HWSZ  = HH * WW;
constexpr int DG    = 16;
constexpr int KK    = 9;

// Scratch (static device buffers; allocation APIs are forbidden)
__device__ float g_t1[(size_t)BATCH * COUT * HWSZ];
__device__ float g_t2[(size_t)BATCH * COUT * HWSZ];
__device__ float g_o4[(size_t)BATCH * (27 * DG) * HWSZ];      // 432 channels
__device__ __align__(16) float g_wt[(size_t)CIN * KK * COUT]; // transposed deform weight [cin][k][o]

// ---------------------------------------------------------------------------
// Packed f32x2 helpers (sm_103a FFMA2 path)
// ---------------------------------------------------------------------------
typedef unsigned long long u64;

__device__ __forceinline__ u64 ffma2(u64 a, u64 b, u64 c) {
    u64 d;
    asm("fma.rn.f32x2 %0, %1, %2, %3;" : "=l"(d) : "l"(a), "l"(b), "l"(c));
    return d;
}
__device__ __forceinline__ u64 pk2(float lo, float hi) {
    u64 r;
    asm("mov.b64 %0, {%1, %2};" : "=l"(r) : "f"(lo), "f"(hi));
    return r;
}
__device__ __forceinline__ float2 upk(u64 v) {
    float2 r;
    asm("mov.b64 {%0, %1}, %2;" : "=f"(r.x), "=f"(r.y) : "l"(v));
    return r;
}

// ---------------------------------------------------------------------------
// Transpose deform weight (COUT, CIN, 3, 3) -> [cin][k][o]
// ---------------------------------------------------------------------------
__global__ void transpose_weight_k(const float* __restrict__ w, float* __restrict__ wt) {
    int idx = blockIdx.x * blockDim.x + threadIdx.x;
    int n = CIN * KK * COUT;
    if (idx >= n) return;
    int o   = idx % COUT;
    int k   = (idx / COUT) % KK;
    int cin = idx / (COUT * KK);
    wt[idx] = w[((size_t)o * CIN + cin) * KK + k];
}

// ---------------------------------------------------------------------------
// Direct 3x3 conv, pad=1, stride=1, optional leaky-relu(0.1).
// Block = (32,4) = 128 threads. Tile: 128 wide x 8 rows, 8 output channels.
// Each thread: 4 px (x) x 2 rows (y) x 8 oc, accumulated as f32x2 pairs.
// Two input channels per smem stage (halves barrier count).
// grid = (H/8, Cout/8, B)
// ---------------------------------------------------------------------------
__global__ void __launch_bounds__(128, 4)
conv3x3_k(const float* __restrict__ in, const float* __restrict__ wgt,
          const float* __restrict__ bias, float* __restrict__ out,
          int Cin, int Cout_, int lrelu) {
    const int tx   = threadIdx.x;        // 0..31
    const int ty   = threadIdx.y;        // 0..3
    const int tid  = ty * 32 + tx;
    const int lane = tid & 31;
    const int warp = tid >> 5;
    const int y0   = blockIdx.x * 8;
    const int oc0  = blockIdx.y * 8;
    const int b    = blockIdx.z;
    const int px0  = tx * 4;

    // s_in[ch][t][col]: t=0..9 covers rows y0-1..y0+8; col 0 and 129 are
    // permanent zero padding (written once), data lives at cols 1..128.
    __shared__ __align__(16) float s_in[2][10][132];
    __shared__ __align__(16) u64 s_w[2][72];  // [ch][o*9+k], lane-duplicated weight

    // init permanent zero-pad edge columns
    for (int i = tid; i < 20; i += 128) {
        s_in[i / 10][i % 10][0]   = 0.f;
        s_in[i / 10][i % 10][129] = 0.f;
    }

    u64 acc[8][2][2];                    // [oc][row][pxpair]
#pragma unroll
    for (int o = 0; o < 8; o++)
#pragma unroll
        for (int i = 0; i < 2; i++) { acc[o][i][0] = 0ull; acc[o][i][1] = 0ull; }

    const float* inb = in + (size_t)b * Cin * HWSZ;

    for (int ci = 0; ci < Cin; ci += 2) {
        __syncthreads();
        // load 2 channels x 10 rows x 128 cols; float4 global load,
        // scalar smem stores (data region starts at col 1 -> no 16B STS).
#pragma unroll
        for (int rr = warp; rr < 20; rr += 4) {
            int ch = rr / 10, t = rr % 10;
            int gy = y0 - 1 + t;
            float4 v = make_float4(0.f, 0.f, 0.f, 0.f);
            if (gy >= 0 && gy < HH) {
                const float* src = inb + (size_t)(ci + ch) * HWSZ + gy * WW;
                v = ((const float4*)src)[lane];
            }
            float* dst = &s_in[ch][t][1 + lane * 4];
            dst[0] = v.x; dst[1] = v.y; dst[2] = v.z; dst[3] = v.w;
        }
        // 144 packed weights, strided over 128 threads
        for (int i = tid; i < 144; i += 128) {
            int ch = i / 72, r = i % 72;
            int o = r / 9, k = r % 9;
            float w = wgt[((size_t)(oc0 + o) * Cin + ci + ch) * 9 + k];
            s_w[ch][r] = pk2(w, w);
        }
        __syncthreads();

#pragma unroll
        for (int ch = 0; ch < 2; ch++) {
            // load 4 rows x 6 cols window, build packed sliding pairs p[r][i]
            u64 p[4][5];
#pragma unroll
            for (int r = 0; r < 4; r++) {
                const float2* row = (const float2*)&s_in[ch][ty * 2 + r][px0];
                float2 v0 = row[0], v1 = row[1], v2 = row[2];
                p[r][0] = pk2(v0.x, v0.y);
                p[r][1] = pk2(v0.y, v1.x);
                p[r][2] = pk2(v1.x, v1.y);
                p[r][3] = pk2(v1.y, v2.x);
                p[r][4] = pk2(v2.x, v2.y);
            }
#pragma unroll
            for (int o = 0; o < 8; o++) {
#pragma unroll
                for (int k = 0; k < 9; k++) {
                    u64 w2 = s_w[ch][o * 9 + k];
                    int r = k / 3, s = k % 3;
                    acc[o][0][0] = ffma2(p[r + 0][s],     w2, acc[o][0][0]);
                    acc[o][0][1] = ffma2(p[r + 0][s + 2], w2, acc[o][0][1]);
                    acc[o][1][0] = ffma2(p[r + 1][s],     w2, acc[o][1][0]);
                    acc[o][1][1] = ffma2(p[r + 1][s + 2], w2, acc[o][1][1]);
                }
            }
        }
    }

    // store with bias (+ optional leaky relu)
#pragma unroll
    for (int o = 0; o < 8; o++) {
        float bv = bias[oc0 + o];
#pragma unroll
        for (int i = 0; i < 2; i++) {
            int yy = y0 + ty * 2 + i;
            float* op = out + ((size_t)b * Cout_ + oc0 + o) * HWSZ + yy * WW + px0;
#pragma unroll
            for (int jp = 0; jp < 2; jp++) {
                float2 v = upk(acc[o][i][jp]);
                v.x += bv; v.y += bv;
                if (lrelu) {
                    v.x = (v.x >= 0.f) ? v.x : 0.1f * v.x;
                    v.y = (v.y >= 0.f) ? v.y : 0.1f * v.y;
                }
                ((float2*)op)[jp] = v;
            }
        }
    }
}

// ---------------------------------------------------------------------------
// Deformable conv (fused tanh/sigmoid on raw conv4 output).
// Thread = one pixel, 64 oc accumulators packed as 32 f32x2.
// Weights for one deform group staged in smem as packed pairs.
// blockDim = (32,4); grid = (W/32, H/4, B)
// ---------------------------------------------------------------------------
__global__ void __launch_bounds__(128, 4)
deform_k(const float* __restrict__ x, const float* __restrict__ o4,
         const float* __restrict__ wt, const float* __restrict__ bias,
         float* __restrict__ out) {
    const int tx = threadIdx.x, ty = threadIdx.y;
    const int tid = ty * 32 + tx;
    const int b   = blockIdx.z;
    const int px  = blockIdx.x * 32 + tx;
    const int py  = blockIdx.y * 4 + ty;
    const int p   = py * WW + px;

    __shared__ __align__(16) u64 s_w[8 * 9 * 32];  // [c][k][oc-pair]

    u64 acc[32];
#pragma unroll
    for (int q = 0; q < 32; q++) acc[q] = 0ull;

    const float* xb = x + (size_t)b * CIN * HWSZ;
    const float* ob = o4 + (size_t)b * (27 * DG) * HWSZ;

    for (int g = 0; g < DG; g++) {
        __syncthreads();
        const u64* wg = (const u64*)(wt + (size_t)g * 8 * 9 * 64);
        for (int i = tid; i < 8 * 9 * 32; i += 128) s_w[i] = wg[i];
        __syncthreads();

        const float* xg = xb + (size_t)g * 8 * HWSZ;

        for (int k = 0; k < KK; k++) {
            float dy = 10.f * tanhf(ob[(size_t)(g * 18 + 2 * k) * HWSZ + p]);
            float dx = 10.f * tanhf(ob[(size_t)(g * 18 + 2 * k + 1) * HWSZ + p]);
            float mv = ob[(size_t)(288 + g * 9 + k) * HWSZ + p];
            float m  = 1.f / (1.f + __expf(-mv));

            float fy = (float)py - 1.f + (float)(k / 3) + dy;
            float fx = (float)px - 1.f + (float)(k % 3) + dx;
            float y0f = floorf(fy), x0f = floorf(fx);
            float ly = fy - y0f, lx = fx - x0f;
            int y0 = (int)y0f, x0 = (int)x0f;
            int y1 = y0 + 1, x1 = x0 + 1;

            bool vy0 = (y0 >= 0) && (y0 < HH);
            bool vy1 = (y1 >= 0) && (y1 < HH);
            bool vx0 = (x0 >= 0) && (x0 < WW);
            bool vx1 = (x1 >= 0) && (x1 < WW);

            float w00 = (1.f - ly) * (1.f - lx) * ((vy0 && vx0) ? m : 0.f);
            float w01 = (1.f - ly) * lx         * ((vy0 && vx1) ? m : 0.f);
            float w10 = ly * (1.f - lx)         * ((vy1 && vx0) ? m : 0.f);
            float w11 = ly * lx                 * ((vy1 && vx1) ? m : 0.f);

            int yc0 = min(max(y0, 0), HH - 1);
            int yc1 = min(max(y1, 0), HH - 1);
            int xc0 = min(max(x0, 0), WW - 1);
            int xc1 = min(max(x1, 0), WW - 1);
            int i00 = yc0 * WW + xc0, i01 = yc0 * WW + xc1;
            int i10 = yc1 * WW + xc0, i11 = yc1 * WW + xc1;

#pragma unroll
            for (int c = 0; c < 8; c++) {
                const float* xc = xg + (size_t)c * HWSZ;
                float v = w00 * xc[i00] + w01 * xc[i01] + w10 * xc[i10] + w11 * xc[i11];
                u64 v2 = pk2(v, v);
                const ulonglong2* wp = (const ulonglong2*)&s_w[(c * 9 + k) * 32];
#pragma unroll
                for (int q = 0; q < 16; q++) {
                    ulonglong2 wq = wp[q];
                    acc[q * 2 + 0] = ffma2(v2, wq.x, acc[q * 2 + 0]);
                    acc[q * 2 + 1] = ffma2(v2, wq.y, acc[q * 2 + 1]);
                }
            }
        }
    }

    float* outb = out + (size_t)b * COUT * HWSZ + p;
#pragma unroll
    for (int q = 0; q < 32; q++) {
        float2 v = upk(acc[q]);
        outb[(size_t)(2 * q + 0) * HWSZ] = v.x + bias[2 * q + 0];
        outb[(size_t)(2 * q + 1) * HWSZ] = v.y + bias[2 * q + 1];
    }
}

// ---------------------------------------------------------------------------
// Launcher
// ---------------------------------------------------------------------------
extern "C" void kernel_launch(void* const* d_in, const int* in_sizes, int n_in,
                              void* d_out, int out_size) {
    const float* x          = (const float*)d_in[0];
    const float* extra_feat = (const float*)d_in[1];
    const float* w1 = (const float*)d_in[2];
    const float* b1 = (const float*)d_in[3];
    const float* w2 = (const float*)d_in[4];
    const float* b2 = (const float*)d_in[5];
    const float* w3 = (const float*)d_in[6];
    const float* b3 = (const float*)d_in[7];
    const float* w4 = (const float*)d_in[8];
    const float* b4 = (const float*)d_in[9];
    const float* weight = (const float*)d_in[10];
    const float* bias   = (const float*)d_in[11];
    float* out = (float*)d_out;

    float *t1, *t2, *o4, *wt;
    cudaGetSymbolAddress((void**)&t1, g_t1);
    cudaGetSymbolAddress((void**)&t2, g_t2);
    cudaGetSymbolAddress((void**)&o4, g_o4);
    cudaGetSymbolAddress((void**)&wt, g_wt);

    dim3 blk(32, 4);

    // Transpose deform weight (only consumer is deform_k, last kernel)
    {
        int n = CIN * KK * COUT;
        transpose_weight_k<<<(n + 255) / 256, 256>>>(weight, wt);
    }

    // conv1: extra_feat (192ch) -> t1 (64ch), lrelu
    conv3x3_k<<<dim3(HH / 8, COUT / 8, BATCH), blk>>>(extra_feat, w1, b1, t1, 3 * COUT, COUT, 1);
    // conv2: t1 -> t2, lrelu
    conv3x3_k<<<dim3(HH / 8, COUT / 8, BATCH), blk>>>(t1, w2, b2, t2, COUT, COUT, 1);
    // conv3: t2 -> t1, lrelu
    conv3x3_k<<<dim3(HH / 8, COUT / 8, BATCH), blk>>>(t2, w3, b3, t1, COUT, COUT, 1);
    // conv4: t1 -> o4 (432ch), no activation (fused into deform)
    conv3x3_k<<<dim3(HH / 8, (27 * DG) / 8, BATCH), blk>>>(t1, w4, b4, o4, COUT, 27 * DG, 0);
    // deformable conv: x + o4 -> out
    deform_k<<<dim3(WW / 32, HH / 4, BATCH), blk>>>(x, o4, wt, bias, out);
}

// round 4
// speedup vs baseline: 1.7826x; 1.1958x over previous
#include <cuda_runtime.h>
#include <cuda_bf16.h>
#include <math.h>

// Problem constants
constexpr int BATCH = 4;
constexpr int CIN   = 128;
constexpr int COUT  = 64;
constexpr int HH    = 128;
constexpr int WW    = 128;
constexpr int HWSZ  = HH * WW;
constexpr int DG    = 16;
constexpr int KK    = 9;

// Scratch (static device buffers; allocation APIs are forbidden)
__device__ float g_t1[(size_t)BATCH * COUT * HWSZ];
__device__ float g_t2[(size_t)BATCH * COUT * HWSZ];
__device__ float g_o4[(size_t)BATCH * (27 * DG) * HWSZ];      // 432 channels
__device__ __align__(16) float g_wt[(size_t)CIN * KK * COUT]; // transposed deform weight [cin][k][o]

// ---------------------------------------------------------------------------
// Packed f32x2 helpers (sm_103a FFMA2 path)
// ---------------------------------------------------------------------------
typedef unsigned long long u64;

__device__ __forceinline__ u64 ffma2(u64 a, u64 b, u64 c) {
    u64 d;
    asm("fma.rn.f32x2 %0, %1, %2, %3;" : "=l"(d) : "l"(a), "l"(b), "l"(c));
    return d;
}
__device__ __forceinline__ u64 pk2(float lo, float hi) {
    u64 r;
    asm("mov.b64 %0, {%1, %2};" : "=l"(r) : "f"(lo), "f"(hi));
    return r;
}
__device__ __forceinline__ float2 upk(u64 v) {
    float2 r;
    asm("mov.b64 {%0, %1}, %2;" : "=f"(r.x), "=f"(r.y) : "l"(v));
    return r;
}

// ---------------------------------------------------------------------------
// Transpose deform weight (COUT, CIN, 3, 3) -> [cin][k][o]
// ---------------------------------------------------------------------------
__global__ void transpose_weight_k(const float* __restrict__ w, float* __restrict__ wt) {
    int idx = blockIdx.x * blockDim.x + threadIdx.x;
    int n = CIN * KK * COUT;
    if (idx >= n) return;
    int o   = idx % COUT;
    int k   = (idx / COUT) % KK;
    int cin = idx / (COUT * KK);
    wt[idx] = w[((size_t)o * CIN + cin) * KK + k];
}

// ---------------------------------------------------------------------------
// Direct 3x3 conv, pad=1, stride=1, optional leaky-relu(0.1).
// Block = (32,4) = 128 threads. Tile: 128 wide x 8 rows, 8 output channels.
// Each thread: 4 px (x) x 2 rows (y) x 8 oc, accumulated as f32x2 pairs.
//
// Smem holds TWO phase-shifted copies of the tile so every sliding input
// pair is an aligned LDS.64 (no mov.b64 pair construction):
//   E[pos] = input col pos           (pairs starting at even cols)
//   O[pos] = input col pos-1         (pairs starting at odd cols; pos 0/129 pad)
// Weights stored [k][o] packed-dup so 1 LDS.128 feeds 2 oc x 4 FFMA2.
// Double-buffered stages: 1 barrier per 2 input channels, loads overlap FMA.
// grid = (H/8, Cout/8, B)
// ---------------------------------------------------------------------------
__global__ void __launch_bounds__(128, 4)
conv3x3_k(const float* __restrict__ in, const float* __restrict__ wgt,
          const float* __restrict__ bias, float* __restrict__ out,
          int Cin, int Cout_, int lrelu) {
    const int tx   = threadIdx.x;        // 0..31
    const int ty   = threadIdx.y;        // 0..3
    const int tid  = ty * 32 + tx;
    const int lane = tid & 31;
    const int warp = tid >> 5;
    const int y0   = blockIdx.x * 8;
    const int oc0  = blockIdx.y * 8;
    const int b    = blockIdx.z;
    const int px0  = tx * 4;

    __shared__ __align__(16) float s_E[2][2][10][132];  // [buf][ch][row][pos]
    __shared__ __align__(16) float s_O[2][2][10][132];
    __shared__ __align__(16) u64   s_w[2][2][9][8];     // [buf][ch][k][o] dup-packed

    // permanent zero pads in O copies (col -1 and col 128 are always OOB)
    for (int i = tid; i < 40; i += 128) {
        int bu = i / 20, ch = (i / 10) % 2, t = i % 10;
        s_O[bu][ch][t][0]   = 0.f;
        s_O[bu][ch][t][129] = 0.f;
    }

    u64 acc[8][2][2];                    // [oc][row][pxpair]
#pragma unroll
    for (int o = 0; o < 8; o++)
#pragma unroll
        for (int i = 0; i < 2; i++) { acc[o][i][0] = 0ull; acc[o][i][1] = 0ull; }

    const float* inb = in + (size_t)b * Cin * HWSZ;

    auto load_stage = [&](int buf, int ci) {
#pragma unroll
        for (int rr = warp; rr < 20; rr += 4) {
            int ch = rr / 10, t = rr % 10;
            int gy = y0 - 1 + t;
            float4 v = make_float4(0.f, 0.f, 0.f, 0.f);
            if (gy >= 0 && gy < HH) {
                const float* src = inb + (size_t)(ci + ch) * HWSZ + gy * WW;
                v = ((const float4*)src)[lane];
            }
            // even-phase copy: aligned STS.128
            *((float4*)&s_E[buf][ch][t][lane * 4]) = v;
            // odd-phase copy (shifted +1): scalar stores
            float* dO = &s_O[buf][ch][t][lane * 4 + 1];
            dO[0] = v.x; dO[1] = v.y; dO[2] = v.z; dO[3] = v.w;
        }
        for (int i = tid; i < 144; i += 128) {
            int ch = i / 72, r = i % 72;
            int k = r / 8, o = r % 8;
            float w = wgt[((size_t)(oc0 + o) * Cin + ci + ch) * 9 + k];
            s_w[buf][ch][k][o] = pk2(w, w);
        }
    };

    load_stage(0, 0);
    __syncthreads();

    for (int ci = 0; ci < Cin; ci += 2) {
        const int buf = (ci >> 1) & 1;
        if (ci + 2 < Cin) load_stage(buf ^ 1, ci + 2);

#pragma unroll
        for (int ch = 0; ch < 2; ch++) {
            // p[r][i] = packed input pair starting at col px0-1+i, row y0+ty*2+r-1
            u64 p[4][5];
#pragma unroll
            for (int r = 0; r < 4; r++) {
                const u64* rowE = (const u64*)&s_E[buf][ch][ty * 2 + r][px0];
                const u64* rowO = (const u64*)&s_O[buf][ch][ty * 2 + r][px0];
                p[r][1] = rowE[0];
                p[r][3] = rowE[1];
                p[r][0] = rowO[0];
                p[r][2] = rowO[1];
                p[r][4] = rowO[2];
            }
#pragma unroll
            for (int k = 0; k < 9; k++) {
                const int r = k / 3, s = k % 3;
                const ulonglong2* wk = (const ulonglong2*)&s_w[buf][ch][k][0];
#pragma unroll
                for (int op = 0; op < 4; op++) {
                    ulonglong2 wq = wk[op];
                    const int o0 = 2 * op, o1 = 2 * op + 1;
                    acc[o0][0][0] = ffma2(p[r + 0][s],     wq.x, acc[o0][0][0]);
                    acc[o0][0][1] = ffma2(p[r + 0][s + 2], wq.x, acc[o0][0][1]);
                    acc[o0][1][0] = ffma2(p[r + 1][s],     wq.x, acc[o0][1][0]);
                    acc[o0][1][1] = ffma2(p[r + 1][s + 2], wq.x, acc[o0][1][1]);
                    acc[o1][0][0] = ffma2(p[r + 0][s],     wq.y, acc[o1][0][0]);
                    acc[o1][0][1] = ffma2(p[r + 0][s + 2], wq.y, acc[o1][0][1]);
                    acc[o1][1][0] = ffma2(p[r + 1][s],     wq.y, acc[o1][1][0]);
                    acc[o1][1][1] = ffma2(p[r + 1][s + 2], wq.y, acc[o1][1][1]);
                }
            }
        }
        __syncthreads();
    }

    // store with bias (+ optional leaky relu)
#pragma unroll
    for (int o = 0; o < 8; o++) {
        float bv = bias[oc0 + o];
#pragma unroll
        for (int i = 0; i < 2; i++) {
            int yy = y0 + ty * 2 + i;
            float* op = out + ((size_t)b * Cout_ + oc0 + o) * HWSZ + yy * WW + px0;
#pragma unroll
            for (int jp = 0; jp < 2; jp++) {
                float2 v = upk(acc[o][i][jp]);
                v.x += bv; v.y += bv;
                if (lrelu) {
                    v.x = (v.x >= 0.f) ? v.x : 0.1f * v.x;
                    v.y = (v.y >= 0.f) ? v.y : 0.1f * v.y;
                }
                ((float2*)op)[jp] = v;
            }
        }
    }
}

// ---------------------------------------------------------------------------
// Deformable conv (fused tanh/sigmoid on raw conv4 output).
// Thread = one pixel, 64 oc accumulators packed as 32 f32x2.
// blockDim = (32,4); grid = (W/32, H/4, B)
// ---------------------------------------------------------------------------
__global__ void __launch_bounds__(128, 4)
deform_k(const float* __restrict__ x, const float* __restrict__ o4,
         const float* __restrict__ wt, const float* __restrict__ bias,
         float* __restrict__ out) {
    const int tx = threadIdx.x, ty = threadIdx.y;
    const int tid = ty * 32 + tx;
    const int b   = blockIdx.z;
    const int px  = blockIdx.x * 32 + tx;
    const int py  = blockIdx.y * 4 + ty;
    const int p   = py * WW + px;

    __shared__ __align__(16) u64 s_w[8 * 9 * 32];  // [c][k][oc-pair]

    u64 acc[32];
#pragma unroll
    for (int q = 0; q < 32; q++) acc[q] = 0ull;

    const float* xb = x + (size_t)b * CIN * HWSZ;
    const float* ob = o4 + (size_t)b * (27 * DG) * HWSZ;

    for (int g = 0; g < DG; g++) {
        __syncthreads();
        const u64* wg = (const u64*)(wt + (size_t)g * 8 * 9 * 64);
        for (int i = tid; i < 8 * 9 * 32; i += 128) s_w[i] = wg[i];
        __syncthreads();

        const float* xg = xb + (size_t)g * 8 * HWSZ;

        for (int k = 0; k < KK; k++) {
            float dy = 10.f * tanhf(ob[(size_t)(g * 18 + 2 * k) * HWSZ + p]);
            float dx = 10.f * tanhf(ob[(size_t)(g * 18 + 2 * k + 1) * HWSZ + p]);
            float mv = ob[(size_t)(288 + g * 9 + k) * HWSZ + p];
            float m  = 1.f / (1.f + __expf(-mv));

            float fy = (float)py - 1.f + (float)(k / 3) + dy;
            float fx = (float)px - 1.f + (float)(k % 3) + dx;
            float y0f = floorf(fy), x0f = floorf(fx);
            float ly = fy - y0f, lx = fx - x0f;
            int y0 = (int)y0f, x0 = (int)x0f;
            int y1 = y0 + 1, x1 = x0 + 1;

            bool vy0 = (y0 >= 0) && (y0 < HH);
            bool vy1 = (y1 >= 0) && (y1 < HH);
            bool vx0 = (x0 >= 0) && (x0 < WW);
            bool vx1 = (x1 >= 0) && (x1 < WW);

            float w00 = (1.f - ly) * (1.f - lx) * ((vy0 && vx0) ? m : 0.f);
            float w01 = (1.f - ly) * lx         * ((vy0 && vx1) ? m : 0.f);
            float w10 = ly * (1.f - lx)         * ((vy1 && vx0) ? m : 0.f);
            float w11 = ly * lx                 * ((vy1 && vx1) ? m : 0.f);

            int yc0 = min(max(y0, 0), HH - 1);
            int yc1 = min(max(y1, 0), HH - 1);
            int xc0 = min(max(x0, 0), WW - 1);
            int xc1 = min(max(x1, 0), WW - 1);
            int i00 = yc0 * WW + xc0, i01 = yc0 * WW + xc1;
            int i10 = yc1 * WW + xc0, i11 = yc1 * WW + xc1;

#pragma unroll
            for (int c = 0; c < 8; c++) {
                const float* xc = xg + (size_t)c * HWSZ;
                float v = w00 * xc[i00] + w01 * xc[i01] + w10 * xc[i10] + w11 * xc[i11];
                u64 v2 = pk2(v, v);
                const ulonglong2* wp = (const ulonglong2*)&s_w[(c * 9 + k) * 32];
#pragma unroll
                for (int q = 0; q < 16; q++) {
                    ulonglong2 wq = wp[q];
                    acc[q * 2 + 0] = ffma2(v2, wq.x, acc[q * 2 + 0]);
                    acc[q * 2 + 1] = ffma2(v2, wq.y, acc[q * 2 + 1]);
                }
            }
        }
    }

    float* outb = out + (size_t)b * COUT * HWSZ + p;
#pragma unroll
    for (int q = 0; q < 32; q++) {
        float2 v = upk(acc[q]);
        outb[(size_t)(2 * q + 0) * HWSZ] = v.x + bias[2 * q + 0];
        outb[(size_t)(2 * q + 1) * HWSZ] = v.y + bias[2 * q + 1];
    }
}

// ---------------------------------------------------------------------------
// Launcher
// ---------------------------------------------------------------------------
extern "C" void kernel_launch(void* const* d_in, const int* in_sizes, int n_in,
                              void* d_out, int out_size) {
    const float* x          = (const float*)d_in[0];
    const float* extra_feat = (const float*)d_in[1];
    const float* w1 = (const float*)d_in[2];
    const float* b1 = (const float*)d_in[3];
    const float* w2 = (const float*)d_in[4];
    const float* b2 = (const float*)d_in[5];
    const float* w3 = (const float*)d_in[6];
    const float* b3 = (const float*)d_in[7];
    const float* w4 = (const float*)d_in[8];
    const float* b4 = (const float*)d_in[9];
    const float* weight = (const float*)d_in[10];
    const float* bias   = (const float*)d_in[11];
    float* out = (float*)d_out;

    float *t1, *t2, *o4, *wt;
    cudaGetSymbolAddress((void**)&t1, g_t1);
    cudaGetSymbolAddress((void**)&t2, g_t2);
    cudaGetSymbolAddress((void**)&o4, g_o4);
    cudaGetSymbolAddress((void**)&wt, g_wt);

    dim3 blk(32, 4);

    // Transpose deform weight (only consumer is deform_k, last kernel)
    {
        int n = CIN * KK * COUT;
        transpose_weight_k<<<(n + 255) / 256, 256>>>(weight, wt);
    }

    // conv1: extra_feat (192ch) -> t1 (64ch), lrelu
    conv3x3_k<<<dim3(HH / 8, COUT / 8, BATCH), blk>>>(extra_feat, w1, b1, t1, 3 * COUT, COUT, 1);
    // conv2: t1 -> t2, lrelu
    conv3x3_k<<<dim3(HH / 8, COUT / 8, BATCH), blk>>>(t1, w2, b2, t2, COUT, COUT, 1);
    // conv3: t2 -> t1, lrelu
    conv3x3_k<<<dim3(HH / 8, COUT / 8, BATCH), blk>>>(t2, w3, b3, t1, COUT, COUT, 1);
    // conv4: t1 -> o4 (432ch), no activation (fused into deform)
    conv3x3_k<<<dim3(HH / 8, (27 * DG) / 8, BATCH), blk>>>(t1, w4, b4, o4, COUT, 27 * DG, 0);
    // deformable conv: x + o4 -> out
    deform_k<<<dim3(WW / 32, HH / 4, BATCH), blk>>>(x, o4, wt, bias, out);
}